// round 3
// baseline (speedup 1.0000x reference)
#include <cuda_runtime.h>
#include <cuda_bf16.h>
#include <cstdint>
#include <cstddef>

#define N_B   2
#define S_LEN 2048
#define HEADS 16
#define HDIM  64
#define EMB   1024
#define SCALE 0.03125f   // 1/sqrt(1024)
#define FULLM 0xffffffffu

// Scratch (alloc-free rule: __device__ globals). All pre-rounded to tf32.
__device__ float g_qp[N_B * S_LEN * EMB];
__device__ float g_kp[N_B * S_LEN * EMB];
__device__ float g_vp[N_B * S_LEN * EMB];
__device__ float g_ao[N_B * S_LEN * EMB];
__device__ float g_wo[EMB * EMB];

// round-to-nearest fp32 -> tf32 (kept as 32-bit pattern)
__device__ __forceinline__ uint32_t f2tf(float x) {
    uint32_t u;
    asm("cvt.rna.tf32.f32 %0, %1;" : "=r"(u) : "f"(x));
    return u;
}
__device__ __forceinline__ float f2tff(float x) { return __uint_as_float(f2tf(x)); }

// D += A(16x8) * B(8x8), tf32 operands, fp32 accum
__device__ __forceinline__ void mma8(float* c, const uint32_t* a, const uint32_t* b) {
    asm volatile(
        "mma.sync.aligned.m16n8k8.row.col.f32.tf32.tf32.f32 "
        "{%0,%1,%2,%3},{%4,%5,%6,%7},{%8,%9},{%0,%1,%2,%3};"
        : "+f"(c[0]), "+f"(c[1]), "+f"(c[2]), "+f"(c[3])
        : "r"(a[0]), "r"(a[1]), "r"(a[2]), "r"(a[3]), "r"(b[0]), "r"(b[1]));
}

__device__ __forceinline__ void cpa16(uint32_t s, const void* g) {
    asm volatile("cp.async.ca.shared.global [%0], [%1], 16;" :: "r"(s), "l"(g));
}
__device__ __forceinline__ void cpa_commit() {
    asm volatile("cp.async.commit_group;");
}

// ---------------------------------------------------------------------------
// Wo pre-round: g_wo = tf32_rna(Wo)
// ---------------------------------------------------------------------------
__global__ __launch_bounds__(256) void cvt_wo(const float* __restrict__ W,
                                              float* __restrict__ Y) {
    int i = (blockIdx.x * 256 + threadIdx.x) * 4;
    float4 v = *(const float4*)(W + i);
    *(float4*)(Y + i) = make_float4(f2tff(v.x), f2tff(v.y), f2tff(v.z), f2tff(v.w));
}

// ---------------------------------------------------------------------------
// Projection: Y(65536x64) = tf32_rna( (X @ W^T) * scale ).  Q gets SCALE.
// grid.y selects (q|k|v).  128 threads = 4 warps x 16 rows.
// ---------------------------------------------------------------------------
__global__ __launch_bounds__(128) void proj_tc(const float* __restrict__ xq,
                                               const float* __restrict__ xk,
                                               const float* __restrict__ xv,
                                               const float* __restrict__ wq,
                                               const float* __restrict__ wk,
                                               const float* __restrict__ wv,
                                               float* __restrict__ yq,
                                               float* __restrict__ yk,
                                               float* __restrict__ yv) {
    __shared__ float Xs[64 * 68];
    __shared__ float Ws[64 * 68];
    const int t = threadIdx.x, lane = t & 31, warp = t >> 5;
    const int tq = lane & 3, gq = lane >> 2;
    const int wm = warp * 16;
    const int rowBase = blockIdx.x * 64;
    const int which = blockIdx.y;
    const float* X = (which == 0) ? xq : (which == 1) ? xk : xv;
    const float* W = (which == 0) ? wq : (which == 1) ? wk : wv;
    float* Y = (which == 0) ? yq : (which == 1) ? yk : yv;
    const float sc = (which == 0) ? SCALE : 1.0f;

#pragma unroll
    for (int i = 0; i < 8; i++) {
        int idx = i * 128 + t;
        int r = idx >> 4, c = (idx & 15) << 2;
        float4 v = *(const float4*)(X + (size_t)(rowBase + r) * 64 + c);
        *(float4*)(&Xs[r * 68 + c]) =
            make_float4(f2tff(v.x), f2tff(v.y), f2tff(v.z), f2tff(v.w));
        float4 w = *(const float4*)(W + r * 64 + c);
        *(float4*)(&Ws[r * 68 + c]) =
            make_float4(f2tff(w.x), f2tff(w.y), f2tff(w.z), f2tff(w.w));
    }
    __syncthreads();

    const uint32_t* Xu = (const uint32_t*)Xs;
    const uint32_t* Wu = (const uint32_t*)Ws;
    float c[8][4] = {};
#pragma unroll
    for (int k = 0; k < 8; k++) {
        uint32_t a[4];
        int kb = k * 8 + tq;
        a[0] = Xu[(wm + gq) * 68 + kb];
        a[1] = Xu[(wm + gq + 8) * 68 + kb];
        a[2] = Xu[(wm + gq) * 68 + kb + 4];
        a[3] = Xu[(wm + gq + 8) * 68 + kb + 4];
#pragma unroll
        for (int nb = 0; nb < 8; nb++) {
            uint32_t b[2] = { Wu[(nb * 8 + gq) * 68 + kb],
                              Wu[(nb * 8 + gq) * 68 + kb + 4] };
            mma8(c[nb], a, b);
        }
    }
#pragma unroll
    for (int nb = 0; nb < 8; nb++) {
        size_t base = (size_t)(rowBase + wm + gq) * 64 + nb * 8 + 2 * tq;
        *(float2*)(Y + base) =
            make_float2(f2tff(c[nb][0] * sc), f2tff(c[nb][1] * sc));
        *(float2*)(Y + base + 8 * 64) =
            make_float2(f2tff(c[nb][2] * sc), f2tff(c[nb][3] * sc));
    }
}

// ---------------------------------------------------------------------------
// Flash attention.  grid = (S/128, N*H), 256 thr = 8 warps, BM=128, BN=64.
// K/V double-buffered via cp.async.  Inputs already tf32-rounded (Q scaled).
// ---------------------------------------------------------------------------
#define KSTR 68
#define VSTR 72
#define KELE (64 * KSTR)
#define VELE (64 * VSTR)
#define STAGE_ELE (KELE + VELE)
#define NT (S_LEN / 64)

extern __shared__ float fa_smem[];

__global__ __launch_bounds__(256) void flash_tc(const float* __restrict__ Q,
                                                const float* __restrict__ K,
                                                const float* __restrict__ V,
                                                float* __restrict__ O) {
    float* smem = fa_smem;
    const int t = threadIdx.x, lane = t & 31, warp = t >> 5;
    const int tq = lane & 3, gq = lane >> 2;
    const int wm = warp * 16;
    const int qt = blockIdx.x, nh = blockIdx.y;
    const int n = nh >> 4, h = nh & 15;
    const size_t headOff = ((size_t)n * S_LEN * HEADS + h) * HDIM;
    const float* qb = Q + headOff;
    const float* kb = K + headOff;
    const float* vb = V + headOff;
    const int q0 = qt * 128;
    const uint32_t sb = (uint32_t)__cvta_generic_to_shared(smem);

    // stage Q tile (128x64, already scaled+tf32) and pull A-fragments
#pragma unroll
    for (int i = 0; i < 8; i++) {
        int idx = i * 256 + t;
        int r = idx >> 4, c = (idx & 15) << 2;
        *(float4*)(&smem[r * KSTR + c]) =
            *(const float4*)(qb + (size_t)(q0 + r) * EMB + c);
    }
    __syncthreads();
    uint32_t aQ[8][4];
    {
        const uint32_t* Qu = (const uint32_t*)smem;
#pragma unroll
        for (int k = 0; k < 8; k++) {
            int kk = k * 8 + tq;
            aQ[k][0] = Qu[(wm + gq) * KSTR + kk];
            aQ[k][1] = Qu[(wm + gq + 8) * KSTR + kk];
            aQ[k][2] = Qu[(wm + gq) * KSTR + kk + 4];
            aQ[k][3] = Qu[(wm + gq + 8) * KSTR + kk + 4];
        }
    }
    __syncthreads();

    // preload tile 0
    {
        const int k0 = 0;
#pragma unroll
        for (int i = 0; i < 4; i++) {
            int id = i * 256 + t;
            int r = id >> 4, c = (id & 15) << 2;
            cpa16(sb + (r * KSTR + c) * 4, kb + (size_t)(k0 + r) * EMB + c);
        }
#pragma unroll
        for (int i = 0; i < 4; i++) {
            int id = i * 256 + t;
            int r = id >> 4, c = (id & 15) << 2;
            cpa16(sb + (KELE + r * VSTR + c) * 4, vb + (size_t)(k0 + r) * EMB + c);
        }
        cpa_commit();
    }

    float o[8][4] = {};
    float m0 = -1e30f, m1 = -1e30f, l0 = 0.f, l1 = 0.f;

    for (int kt = 0; kt < NT; kt++) {
        const int buf = kt & 1;
        if (kt + 1 < NT) {
            const int k0 = (kt + 1) * 64;
            const uint32_t dst = sb + (buf ^ 1) * STAGE_ELE * 4;
#pragma unroll
            for (int i = 0; i < 4; i++) {
                int id = i * 256 + t;
                int r = id >> 4, c = (id & 15) << 2;
                cpa16(dst + (r * KSTR + c) * 4, kb + (size_t)(k0 + r) * EMB + c);
            }
#pragma unroll
            for (int i = 0; i < 4; i++) {
                int id = i * 256 + t;
                int r = id >> 4, c = (id & 15) << 2;
                cpa16(dst + (KELE + r * VSTR + c) * 4,
                      vb + (size_t)(k0 + r) * EMB + c);
            }
            cpa_commit();
            asm volatile("cp.async.wait_group 1;");
        } else {
            asm volatile("cp.async.wait_group 0;");
        }
        __syncthreads();

        const uint32_t* Ku = (const uint32_t*)(smem + buf * STAGE_ELE);
        const uint32_t* Vu = (const uint32_t*)(smem + buf * STAGE_ELE + KELE);

        // S = Q K^T  (scale baked into Q)
        float c_[8][4] = {};
#pragma unroll
        for (int k = 0; k < 8; k++) {
            int kk = k * 8 + tq;
#pragma unroll
            for (int nb = 0; nb < 8; nb++) {
                uint32_t b[2] = { Ku[(nb * 8 + gq) * KSTR + kk],
                                  Ku[(nb * 8 + gq) * KSTR + kk + 4] };
                mma8(c_[nb], aQ[k], b);
            }
        }

        // online softmax: rows (wm+gq) -> c0,c1 ; (wm+gq+8) -> c2,c3
        float mt0 = -1e30f, mt1 = -1e30f;
#pragma unroll
        for (int nb = 0; nb < 8; nb++) {
            mt0 = fmaxf(mt0, fmaxf(c_[nb][0], c_[nb][1]));
            mt1 = fmaxf(mt1, fmaxf(c_[nb][2], c_[nb][3]));
        }
#pragma unroll
        for (int off = 1; off <= 2; off <<= 1) {
            mt0 = fmaxf(mt0, __shfl_xor_sync(FULLM, mt0, off));
            mt1 = fmaxf(mt1, __shfl_xor_sync(FULLM, mt1, off));
        }
        float mn0 = fmaxf(m0, mt0), mn1 = fmaxf(m1, mt1);
        float al0 = __expf(m0 - mn0), al1 = __expf(m1 - mn1);
        m0 = mn0; m1 = mn1;
        float rs0 = 0.f, rs1 = 0.f;
#pragma unroll
        for (int nb = 0; nb < 8; nb++) {
            c_[nb][0] = __expf(c_[nb][0] - mn0); rs0 += c_[nb][0];
            c_[nb][1] = __expf(c_[nb][1] - mn0); rs0 += c_[nb][1];
            c_[nb][2] = __expf(c_[nb][2] - mn1); rs1 += c_[nb][2];
            c_[nb][3] = __expf(c_[nb][3] - mn1); rs1 += c_[nb][3];
        }
#pragma unroll
        for (int off = 1; off <= 2; off <<= 1) {
            rs0 += __shfl_xor_sync(FULLM, rs0, off);
            rs1 += __shfl_xor_sync(FULLM, rs1, off);
        }
        l0 = l0 * al0 + rs0;
        l1 = l1 * al1 + rs1;
#pragma unroll
        for (int nb = 0; nb < 8; nb++) {
            o[nb][0] *= al0; o[nb][1] *= al0;
            o[nb][2] *= al1; o[nb][3] *= al1;
            c_[nb][0] = f2tff(c_[nb][0]); c_[nb][1] = f2tff(c_[nb][1]);
            c_[nb][2] = f2tff(c_[nb][2]); c_[nb][3] = f2tff(c_[nb][3]);
        }

        // O += P V : C-frag (cols 2q,2q+1) -> A-frag (cols q,q+4) via shfl
        const int src = (lane & ~3) + (tq >> 1);
        const bool oddq = (tq & 1);
#pragma unroll
        for (int kg = 0; kg < 8; kg++) {
            uint32_t aP[4];
            float x0 = __shfl_sync(FULLM, c_[kg][0], src);
            float x1 = __shfl_sync(FULLM, c_[kg][1], src);
            aP[0] = __float_as_uint(oddq ? x1 : x0);
            x0 = __shfl_sync(FULLM, c_[kg][2], src);
            x1 = __shfl_sync(FULLM, c_[kg][3], src);
            aP[1] = __float_as_uint(oddq ? x1 : x0);
            x0 = __shfl_sync(FULLM, c_[kg][0], src + 2);
            x1 = __shfl_sync(FULLM, c_[kg][1], src + 2);
            aP[2] = __float_as_uint(oddq ? x1 : x0);
            x0 = __shfl_sync(FULLM, c_[kg][2], src + 2);
            x1 = __shfl_sync(FULLM, c_[kg][3], src + 2);
            aP[3] = __float_as_uint(oddq ? x1 : x0);
#pragma unroll
            for (int nb = 0; nb < 8; nb++) {
                uint32_t b[2] = { Vu[(kg * 8 + tq) * VSTR + nb * 8 + gq],
                                  Vu[(kg * 8 + tq + 4) * VSTR + nb * 8 + gq] };
                mma8(o[nb], aP, b);
            }
        }
        __syncthreads();
    }

    const float inv0 = 1.0f / l0, inv1 = 1.0f / l1;
#pragma unroll
    for (int nb = 0; nb < 8; nb++) {
        size_t base = headOff + (size_t)(q0 + wm + gq) * EMB + nb * 8 + 2 * tq;
        *(float2*)(O + base) =
            make_float2(f2tff(o[nb][0] * inv0), f2tff(o[nb][1] * inv0));
        *(float2*)(O + base + (size_t)8 * EMB) =
            make_float2(f2tff(o[nb][2] * inv1), f2tff(o[nb][3] * inv1));
    }
}

// ---------------------------------------------------------------------------
// Output GEMM: Y(4096x1024) = X @ Wo^T + bo.  BM=128, BN=64, BK=32.
// 256 thr = 8 warps.  X(=ao) and W(=g_wo) pre-rounded; cp.async pipeline.
// ---------------------------------------------------------------------------
#define OSTR 36
#define XELE (128 * OSTR)
#define WELE (64 * OSTR)
#define OSTAGE (XELE + WELE)
#define NKT (EMB / 32)

extern __shared__ float og_smem[];

__global__ __launch_bounds__(256) void out_tc(const float* __restrict__ X,
                                              const float* __restrict__ W,
                                              const float* __restrict__ bias,
                                              float* __restrict__ Y) {
    float* smem = og_smem;
    const int t = threadIdx.x, lane = t & 31, warp = t >> 5;
    const int tq = lane & 3, gq = lane >> 2;
    const int wm = warp * 16;
    const int m0 = blockIdx.x * 128, n0 = blockIdx.y * 64;
    const uint32_t sb = (uint32_t)__cvta_generic_to_shared(smem);

    // preload k-tile 0
    {
#pragma unroll
        for (int i = 0; i < 4; i++) {
            int id = i * 256 + t;
            int r = id >> 3, c = (id & 7) << 2;
            cpa16(sb + (r * OSTR + c) * 4, X + (size_t)(m0 + r) * EMB + c);
        }
#pragma unroll
        for (int i = 0; i < 2; i++) {
            int id = i * 256 + t;
            int r = id >> 3, c = (id & 7) << 2;
            cpa16(sb + (XELE + r * OSTR + c) * 4, W + (size_t)(n0 + r) * EMB + c);
        }
        cpa_commit();
    }

    float acc[8][4] = {};
    for (int kt = 0; kt < NKT; kt++) {
        const int buf = kt & 1;
        if (kt + 1 < NKT) {
            const int k0 = (kt + 1) * 32;
            const uint32_t dst = sb + (buf ^ 1) * OSTAGE * 4;
#pragma unroll
            for (int i = 0; i < 4; i++) {
                int id = i * 256 + t;
                int r = id >> 3, c = (id & 7) << 2;
                cpa16(dst + (r * OSTR + c) * 4, X + (size_t)(m0 + r) * EMB + k0 + c);
            }
#pragma unroll
            for (int i = 0; i < 2; i++) {
                int id = i * 256 + t;
                int r = id >> 3, c = (id & 7) << 2;
                cpa16(dst + (XELE + r * OSTR + c) * 4,
                      W + (size_t)(n0 + r) * EMB + k0 + c);
            }
            cpa_commit();
            asm volatile("cp.async.wait_group 1;");
        } else {
            asm volatile("cp.async.wait_group 0;");
        }
        __syncthreads();

        const uint32_t* Xu = (const uint32_t*)(smem + buf * OSTAGE);
        const uint32_t* Wu = (const uint32_t*)(smem + buf * OSTAGE + XELE);
#pragma unroll
        for (int k = 0; k < 4; k++) {
            int kk = k * 8 + tq;
            uint32_t a[4];
            a[0] = Xu[(wm + gq) * OSTR + kk];
            a[1] = Xu[(wm + gq + 8) * OSTR + kk];
            a[2] = Xu[(wm + gq) * OSTR + kk + 4];
            a[3] = Xu[(wm + gq + 8) * OSTR + kk + 4];
#pragma unroll
            for (int nb = 0; nb < 8; nb++) {
                uint32_t b[2] = { Wu[(nb * 8 + gq) * OSTR + kk],
                                  Wu[(nb * 8 + gq) * OSTR + kk + 4] };
                mma8(acc[nb], a, b);
            }
        }
        __syncthreads();
    }

#pragma unroll
    for (int nb = 0; nb < 8; nb++) {
        int col = n0 + nb * 8 + 2 * tq;
        float b0 = __ldg(bias + col), b1 = __ldg(bias + col + 1);
        size_t base = (size_t)(m0 + wm + gq) * EMB + col;
        *(float2*)(Y + base) = make_float2(acc[nb][0] + b0, acc[nb][1] + b1);
        *(float2*)(Y + base + (size_t)8 * EMB) =
            make_float2(acc[nb][2] + b0, acc[nb][3] + b1);
    }
}

// ---------------------------------------------------------------------------
extern "C" void kernel_launch(void* const* d_in, const int* in_sizes, int n_in,
                              void* d_out, int out_size) {
    const float* q  = (const float*)d_in[0];
    const float* k  = (const float*)d_in[1];
    const float* v  = (const float*)d_in[2];
    const float* Wq = (const float*)d_in[3];
    const float* Wk = (const float*)d_in[4];
    const float* Wv = (const float*)d_in[5];
    const float* Wo = (const float*)d_in[6];
    const float* bo = (const float*)d_in[7];
    float* out = (float*)d_out;

    float *qp, *kp, *vp, *ao, *wo;
    cudaGetSymbolAddress((void**)&qp, g_qp);
    cudaGetSymbolAddress((void**)&kp, g_kp);
    cudaGetSymbolAddress((void**)&vp, g_vp);
    cudaGetSymbolAddress((void**)&ao, g_ao);
    cudaGetSymbolAddress((void**)&wo, g_wo);

    static bool attr_done = false;
    if (!attr_done) {
        cudaFuncSetAttribute(flash_tc, cudaFuncAttributeMaxDynamicSharedMemorySize,
                             2 * STAGE_ELE * 4);
        cudaFuncSetAttribute(out_tc, cudaFuncAttributeMaxDynamicSharedMemorySize,
                             2 * OSTAGE * 4);
        attr_done = true;
    }

    cvt_wo<<<1024, 256>>>(Wo, wo);
    proj_tc<<<dim3(1024, 3), 128>>>(q, k, v, Wq, Wk, Wv, qp, kp, vp);
    flash_tc<<<dim3(S_LEN / 128, N_B * HEADS), 256, 2 * STAGE_ELE * 4>>>(qp, kp, vp, ao);
    out_tc<<<dim3((N_B * S_LEN) / 128, EMB / 64), 256, 2 * OSTAGE * 4>>>(ao, wo, bo, out);
}